// round 14
// baseline (speedup 1.0000x reference)
#include <cuda_runtime.h>
#include <math.h>

// ---------------- scratch (static device allocation, no cudaMalloc) ----------------
__device__ float g_buf1[512 * 16 * 2048];   // conv1 out
__device__ float g_buf2[512 * 32 * 1024];   // conv2 out
__device__ float g_buf3[512 * 2048];        // conv3 + avgpool out (flattened features)
__device__ float g_buf4[512 * 4096];        // linear out  [B][64][64]
__device__ float g_buf5[512 * 4096];        // mamba1 out

// ============================================================================
// conv1 (1->16, k=5, pad=2) + relu + maxpool2.  x:[512,4096] -> out:[512,16,2048]
// ============================================================================
__global__ void k_conv1(const float* __restrict__ x, const float* __restrict__ w,
                        const float* __restrict__ bias, float* __restrict__ out) {
    __shared__ float xs[516];
    __shared__ float ws[80];
    __shared__ float bs[16];
    const int b = blockIdx.y;
    const int base = blockIdx.x * 256;          // output position base
    const int in_start = base * 2 - 2;
    const int tid = threadIdx.x;

    for (int i = tid; i < 516; i += 256) {
        int p = in_start + i;
        xs[i] = (p >= 0 && p < 4096) ? x[b * 4096 + p] : 0.f;
    }
    if (tid < 80) ws[tid] = w[tid];
    if (tid < 16) bs[tid] = bias[tid];
    __syncthreads();

    float xv[6];
#pragma unroll
    for (int j = 0; j < 6; j++) xv[j] = xs[2 * tid + j];

#pragma unroll
    for (int c = 0; c < 16; c++) {
        float a0 = 0.f, a1 = 0.f;
#pragma unroll
        for (int k = 0; k < 5; k++) {
            float wv = ws[c * 5 + k];
            a0 = fmaf(wv, xv[k], a0);
            a1 = fmaf(wv, xv[k + 1], a1);
        }
        out[(b * 16 + c) * 2048 + base + tid] = fmaxf(fmaxf(a0, a1) + bs[c], 0.f);
    }
}

// ============================================================================
// conv2 (16->32, k=5, pad=2) + relu + maxpool2. [512,16,2048] -> [512,32,1024]
// block: 256 threads = 32 oc x 8 pos-groups; 64 out positions per block
// ============================================================================
__global__ void k_conv2(const float* __restrict__ in, const float* __restrict__ w,
                        const float* __restrict__ bias, float* __restrict__ out) {
    __shared__ float xs[16][132];
    __shared__ float ws[16 * 5 * 32];   // [ic][k][oc] transposed
    __shared__ float bs[32];
    const int b = blockIdx.y;
    const int base = blockIdx.x * 64;     // output position base
    const int in_start = base * 2 - 2;
    const int tid = threadIdx.x;

    for (int idx = tid; idx < 16 * 132; idx += 256) {
        int ic = idx / 132, i = idx % 132;
        int p = in_start + i;
        xs[ic][i] = (p >= 0 && p < 2048) ? in[(b * 16 + ic) * 2048 + p] : 0.f;
    }
    for (int idx = tid; idx < 2560; idx += 256) {
        int oc = idx / 80, r = idx % 80;  // r = ic*5+k
        ws[r * 32 + oc] = w[idx];
    }
    if (tid < 32) bs[tid] = bias[tid];
    __syncthreads();

    const int oc = tid & 31, pg = tid >> 5;
    const int cbase = pg * 16;            // conv-local base (= 2*p0_loc)

    float acc[16];
#pragma unroll
    for (int q = 0; q < 16; q++) acc[q] = 0.f;

    for (int ic = 0; ic < 16; ic++) {
        float xv[20];
#pragma unroll
        for (int j = 0; j < 20; j++) xv[j] = xs[ic][cbase + j];
        float wv[5];
#pragma unroll
        for (int k = 0; k < 5; k++) wv[k] = ws[(ic * 5 + k) * 32 + oc];
#pragma unroll
        for (int q = 0; q < 16; q++)
#pragma unroll
            for (int k = 0; k < 5; k++)
                acc[q] = fmaf(wv[k], xv[q + k], acc[q]);
    }
    const float bv = bs[oc];
#pragma unroll
    for (int i = 0; i < 8; i++) {
        float v = fmaxf(fmaxf(acc[2 * i], acc[2 * i + 1]) + bv, 0.f);
        out[(b * 32 + oc) * 1024 + base + pg * 8 + i] = v;
    }
}

// ============================================================================
// conv3 (32->64, k=5, pad=2) + relu + adaptive avgpool(32) fused.
// [512,32,1024] -> [512,64,32] stored flat [512,2048] (c major, window minor)
// grid (4, 512): 8 pool windows per block. block 256 = 64 oc x 4 pos-groups.
// dynamic smem: xs 32*260 + ws 10240 + bias 64 + red 2048 = 20672 floats
// ============================================================================
__global__ void k_conv3(const float* __restrict__ in, const float* __restrict__ w,
                        const float* __restrict__ bias, float* __restrict__ out) {
    extern __shared__ float s3[];
    float* xs = s3;                 // [32][260]
    float* ws = s3 + 32 * 260;      // [ic][k][oc] = 10240
    float* bs = ws + 10240;         // 64
    float* red = bs + 64;           // [pg][oc][wl] = 4*64*8

    const int b = blockIdx.y;
    const int wbase = blockIdx.x * 8;
    const int in_start = wbase * 32 - 2;
    const int tid = threadIdx.x;

    for (int idx = tid; idx < 32 * 260; idx += 256) {
        int ic = idx / 260, i = idx % 260;
        int p = in_start + i;
        xs[ic * 260 + i] = (p >= 0 && p < 1024) ? in[(b * 32 + ic) * 1024 + p] : 0.f;
    }
    for (int idx = tid; idx < 10240; idx += 256) {
        int oc = idx / 160, r = idx % 160;  // r = ic*5+k
        ws[r * 64 + oc] = w[idx];
    }
    if (tid < 64) bs[tid] = bias[tid];
    __syncthreads();

    const int oc = tid & 63, pg = tid >> 6;
    const float bv = bs[oc];

    for (int wl = 0; wl < 8; wl++) {
        float acc[8];
#pragma unroll
        for (int i = 0; i < 8; i++) acc[i] = 0.f;
        const int xoff = wl * 32 + pg * 8;
        for (int ic = 0; ic < 32; ic++) {
            float xv[12];
#pragma unroll
            for (int j = 0; j < 12; j++) xv[j] = xs[ic * 260 + xoff + j];
            float wv[5];
#pragma unroll
            for (int k = 0; k < 5; k++) wv[k] = ws[(ic * 5 + k) * 64 + oc];
#pragma unroll
            for (int i = 0; i < 8; i++)
#pragma unroll
                for (int k = 0; k < 5; k++)
                    acc[i] = fmaf(wv[k], xv[i + k], acc[i]);
        }
        float part = 0.f;
#pragma unroll
        for (int i = 0; i < 8; i++) part += fmaxf(acc[i] + bv, 0.f);
        red[(pg * 64 + oc) * 8 + wl] = part;
    }
    __syncthreads();
    for (int idx = tid; idx < 512; idx += 256) {
        int o = idx >> 3, wl = idx & 7;
        float ssum = red[(0 * 64 + o) * 8 + wl] + red[(1 * 64 + o) * 8 + wl] +
                     red[(2 * 64 + o) * 8 + wl] + red[(3 * 64 + o) * 8 + wl];
        out[b * 2048 + o * 32 + wbase + wl] = ssum * (1.f / 32.f);
    }
}

// ============================================================================
// linear: C[512,4096] = A[512,2048] @ Bw[4096,2048]^T + bias
// 64x64 block tile, BK=16, 256 threads, 4x4 microtile
// ============================================================================
__global__ void k_gemm(const float* __restrict__ A, const float* __restrict__ Bw,
                       const float* __restrict__ bias, float* __restrict__ C) {
    __shared__ float As[16][68];
    __shared__ float Bs[16][68];
    const int bm = blockIdx.y * 64, bn = blockIdx.x * 64;
    const int tid = threadIdx.x;
    const int tx = tid & 15, ty = tid >> 4;
    const int r = tid >> 2, kq = tid & 3;

    float acc[4][4];
#pragma unroll
    for (int i = 0; i < 4; i++)
#pragma unroll
        for (int j = 0; j < 4; j++) acc[i][j] = 0.f;

    const float* Ap = A + (bm + r) * 2048 + kq * 4;
    const float* Bp = Bw + (bn + r) * 2048 + kq * 4;

    for (int k0 = 0; k0 < 2048; k0 += 16) {
        float4 av = *(const float4*)(Ap + k0);
        float4 bv = *(const float4*)(Bp + k0);
        As[kq * 4 + 0][r] = av.x; As[kq * 4 + 1][r] = av.y;
        As[kq * 4 + 2][r] = av.z; As[kq * 4 + 3][r] = av.w;
        Bs[kq * 4 + 0][r] = bv.x; Bs[kq * 4 + 1][r] = bv.y;
        Bs[kq * 4 + 2][r] = bv.z; Bs[kq * 4 + 3][r] = bv.w;
        __syncthreads();
#pragma unroll
        for (int k = 0; k < 16; k++) {
            float4 a = *(const float4*)&As[k][ty * 4];
            float4 b4 = *(const float4*)&Bs[k][tx * 4];
            acc[0][0] = fmaf(a.x, b4.x, acc[0][0]); acc[0][1] = fmaf(a.x, b4.y, acc[0][1]);
            acc[0][2] = fmaf(a.x, b4.z, acc[0][2]); acc[0][3] = fmaf(a.x, b4.w, acc[0][3]);
            acc[1][0] = fmaf(a.y, b4.x, acc[1][0]); acc[1][1] = fmaf(a.y, b4.y, acc[1][1]);
            acc[1][2] = fmaf(a.y, b4.z, acc[1][2]); acc[1][3] = fmaf(a.y, b4.w, acc[1][3]);
            acc[2][0] = fmaf(a.z, b4.x, acc[2][0]); acc[2][1] = fmaf(a.z, b4.y, acc[2][1]);
            acc[2][2] = fmaf(a.z, b4.z, acc[2][2]); acc[2][3] = fmaf(a.z, b4.w, acc[2][3]);
            acc[3][0] = fmaf(a.w, b4.x, acc[3][0]); acc[3][1] = fmaf(a.w, b4.y, acc[3][1]);
            acc[3][2] = fmaf(a.w, b4.z, acc[3][2]); acc[3][3] = fmaf(a.w, b4.w, acc[3][3]);
        }
        __syncthreads();
    }
    const float b0 = bias[bn + tx * 4 + 0];
    const float b1 = bias[bn + tx * 4 + 1];
    const float b2 = bias[bn + tx * 4 + 2];
    const float b3 = bias[bn + tx * 4 + 3];
#pragma unroll
    for (int i = 0; i < 4; i++) {
        float4 o = make_float4(acc[i][0] + b0, acc[i][1] + b1, acc[i][2] + b2, acc[i][3] + b3);
        *(float4*)&C[(bm + ty * 4 + i) * 4096 + bn + tx * 4] = o;
    }
}

// ============================================================================
// fused layernorm + mamba block. One CTA per batch element, L=64, d=64.
// ============================================================================
__global__ void k_mamba(const float* __restrict__ xin,
                        const float* __restrict__ lng, const float* __restrict__ lnb,
                        const float* __restrict__ inw, const float* __restrict__ cvw,
                        const float* __restrict__ cvb, const float* __restrict__ xpw,
                        const float* __restrict__ dtw, const float* __restrict__ dtb,
                        const float* __restrict__ al,  const float* __restrict__ dp,
                        const float* __restrict__ ow,  float* __restrict__ outp) {
    extern __shared__ float s[];
    float* xT    = s;             // [64][68]  layernormed x, transposed [d][l]
    float* wT    = s + 4352;      // [64][132] in_w transposed [d][e]
    float* owT   = s + 12800;     // [64][68]  ow transposed [d][e]
    float* z_s   = s + 17152;     // [64][65]  [l][d]
    float* xi_s  = s + 21312;     // [64][65]
    float* u_s   = s + 25472;     // [64][65]
    float* dt_s  = s + 29632;     // [64][65]
    float* y2T   = s + 33792;     // [64][68]  [d][l]
    float* xdbl  = s + 38144;     // [64][13]
    float* xpw_s = s + 38976;     // 768
    float* dtw_s = s + 39744;     // 256
    float* dtb_s = s + 40000;
    float* cvw_s = s + 40064;     // 128
    float* cvb_s = s + 40192;
    float* dp_s  = s + 40256;
    float* lng_s = s + 40320;
    float* lnb_s = s + 40384;

    const int b = blockIdx.x, tid = threadIdx.x;
    const float* xb = xin + b * 4096;

    // ---- load weights (coalesced global, conflict-free transposed STS) ----
    for (int idx = tid; idx < 8192; idx += 256) {
        int e = idx >> 6, d = idx & 63;
        wT[d * 132 + e] = inw[idx];
    }
    for (int idx = tid; idx < 4096; idx += 256) {
        int e = idx >> 6, d = idx & 63;
        owT[d * 68 + e] = ow[idx];
    }
    for (int idx = tid; idx < 768; idx += 256) xpw_s[idx] = xpw[idx];
    dtw_s[tid] = dtw[tid];                      // exactly 256
    if (tid < 64) {
        dtb_s[tid] = dtb[tid]; cvb_s[tid] = cvb[tid]; dp_s[tid] = dp[tid];
        lng_s[tid] = lng[tid]; lnb_s[tid] = lnb[tid];
    }
    if (tid < 128) cvw_s[tid] = cvw[tid];
    __syncthreads();

    // ---- layernorm (4 threads per row), write transposed ----
    {
        const int l = tid >> 2, j = tid & 3;
        const float* row = xb + l * 64;
        float4 v[4];
#pragma unroll
        for (int i = 0; i < 4; i++) v[i] = *(const float4*)(row + j * 16 + i * 4);
        float sm = 0.f;
#pragma unroll
        for (int i = 0; i < 4; i++) sm += v[i].x + v[i].y + v[i].z + v[i].w;
        sm += __shfl_xor_sync(0xffffffffu, sm, 1);
        sm += __shfl_xor_sync(0xffffffffu, sm, 2);
        const float mean = sm * (1.f / 64.f);
        float vs = 0.f;
#pragma unroll
        for (int i = 0; i < 4; i++) {
            float a = v[i].x - mean, bb = v[i].y - mean, c = v[i].z - mean, dd = v[i].w - mean;
            vs += a * a + bb * bb + c * c + dd * dd;
        }
        vs += __shfl_xor_sync(0xffffffffu, vs, 1);
        vs += __shfl_xor_sync(0xffffffffu, vs, 2);
        const float rstd = rsqrtf(vs * (1.f / 64.f) + 1e-5f);
#pragma unroll
        for (int i = 0; i < 4; i++) {
            int d0 = j * 16 + i * 4;
            xT[(d0 + 0) * 68 + l] = (v[i].x - mean) * rstd * lng_s[d0 + 0] + lnb_s[d0 + 0];
            xT[(d0 + 1) * 68 + l] = (v[i].y - mean) * rstd * lng_s[d0 + 1] + lnb_s[d0 + 1];
            xT[(d0 + 2) * 68 + l] = (v[i].z - mean) * rstd * lng_s[d0 + 2] + lnb_s[d0 + 2];
            xT[(d0 + 3) * 68 + l] = (v[i].w - mean) * rstd * lng_s[d0 + 3] + lnb_s[d0 + 3];
        }
    }
    __syncthreads();

    // ---- in_proj: xz[l][e] = sum_d xT[d][l] * wT[d][e]   (4l x 8e microtile) ----
    {
        const int tl = tid & 15, te = tid >> 4;
        float acc[4][8];
#pragma unroll
        for (int i = 0; i < 4; i++)
#pragma unroll
            for (int j = 0; j < 8; j++) acc[i][j] = 0.f;
        const float* xcol = xT + tl * 4;
        const float* wcol = wT + te * 8;
        for (int d = 0; d < 64; d++) {
            float4 xv = *(const float4*)(xcol + d * 68);
            float4 w0 = *(const float4*)(wcol + d * 132);
            float4 w1 = *(const float4*)(wcol + d * 132 + 4);
            float xa[4] = {xv.x, xv.y, xv.z, xv.w};
#pragma unroll
            for (int i = 0; i < 4; i++) {
                acc[i][0] = fmaf(xa[i], w0.x, acc[i][0]);
                acc[i][1] = fmaf(xa[i], w0.y, acc[i][1]);
                acc[i][2] = fmaf(xa[i], w0.z, acc[i][2]);
                acc[i][3] = fmaf(xa[i], w0.w, acc[i][3]);
                acc[i][4] = fmaf(xa[i], w1.x, acc[i][4]);
                acc[i][5] = fmaf(xa[i], w1.y, acc[i][5]);
                acc[i][6] = fmaf(xa[i], w1.z, acc[i][6]);
                acc[i][7] = fmaf(xa[i], w1.w, acc[i][7]);
            }
        }
        const bool isz = (te >= 8);
        float* dst = isz ? z_s : xi_s;
        const int ebase = (isz ? (te - 8) : te) * 8;
#pragma unroll
        for (int i = 0; i < 4; i++)
#pragma unroll
            for (int j = 0; j < 8; j++)
                dst[(tl * 4 + i) * 65 + ebase + j] = acc[i][j];
    }
    __syncthreads();

    // ---- causal depthwise conv (k=2) + silu -> u ----
    for (int idx = tid; idx < 4096; idx += 256) {
        int l = idx >> 6, d = idx & 63;
        float xc = fmaf(cvw_s[d * 2 + 1], xi_s[l * 65 + d], cvb_s[d]);
        if (l > 0) xc = fmaf(cvw_s[d * 2], xi_s[(l - 1) * 65 + d], xc);
        u_s[l * 65 + d] = xc / (1.f + expf(-xc));
    }
    __syncthreads();

    // ---- x_proj: xdbl[l][j] = sum_d u[l][d] * xpw[j][d] ----
    for (int idx = tid; idx < 768; idx += 256) {
        int l = idx / 12, j = idx % 12;
        const float* ur = u_s + l * 65;
        const float* wr = xpw_s + j * 64;
        float sm = 0.f;
#pragma unroll 8
        for (int d = 0; d < 64; d++) sm = fmaf(ur[d], wr[d], sm);
        xdbl[l * 13 + j] = sm;
    }
    __syncthreads();

    // ---- dt = softplus(xdbl[:, :4] @ dtw^T + dtb) ----
    for (int idx = tid; idx < 4096; idx += 256) {
        int l = idx >> 6, d = idx & 63;
        float v = dtb_s[d];
#pragma unroll
        for (int r2 = 0; r2 < 4; r2++) v = fmaf(xdbl[l * 13 + r2], dtw_s[d * 4 + r2], v);
        dt_s[l * 65 + d] = fmaxf(v, 0.f) + log1pf(expf(-fabsf(v)));
    }
    __syncthreads();

    // ---- selective scan: thread (d = tid>>2, n = tid&3) ----
    {
        const int d = tid >> 2, n = tid & 3;
        const float A = -expf(al[d * 4 + n]);
        const float dpv = dp_s[d];
        float h = 0.f;
        for (int t = 0; t < 64; t++) {
            float dtv = dt_s[t * 65 + d];
            float uv = u_s[t * 65 + d];
            float Bv = xdbl[t * 13 + 4 + n];
            float Cv = xdbl[t * 13 + 8 + n];
            float dA = expf(dtv * A);
            h = fmaf(dA, h, dtv * Bv * uv);
            float yp = h * Cv;
            yp += __shfl_xor_sync(0xffffffffu, yp, 1);
            yp += __shfl_xor_sync(0xffffffffu, yp, 2);
            if (n == 0) {
                float zv = z_s[t * 65 + d];
                float yv = fmaf(dpv, uv, yp);
                y2T[d * 68 + t] = yv * (zv / (1.f + expf(-zv)));
            }
        }
    }
    __syncthreads();

    // ---- out_proj: out[l][e] = sum_d y2T[d][l] * owT[d][e]   (4x4 microtile) ----
    {
        const int tl = tid & 15, te = tid >> 4;
        float acc[4][4];
#pragma unroll
        for (int i = 0; i < 4; i++)
#pragma unroll
            for (int j = 0; j < 4; j++) acc[i][j] = 0.f;
        const float* ycol = y2T + tl * 4;
        const float* wcol = owT + te * 4;
        for (int d = 0; d < 64; d++) {
            float4 yv = *(const float4*)(ycol + d * 68);
            float4 wv = *(const float4*)(wcol + d * 68);
            acc[0][0] = fmaf(yv.x, wv.x, acc[0][0]); acc[0][1] = fmaf(yv.x, wv.y, acc[0][1]);
            acc[0][2] = fmaf(yv.x, wv.z, acc[0][2]); acc[0][3] = fmaf(yv.x, wv.w, acc[0][3]);
            acc[1][0] = fmaf(yv.y, wv.x, acc[1][0]); acc[1][1] = fmaf(yv.y, wv.y, acc[1][1]);
            acc[1][2] = fmaf(yv.y, wv.z, acc[1][2]); acc[1][3] = fmaf(yv.y, wv.w, acc[1][3]);
            acc[2][0] = fmaf(yv.z, wv.x, acc[2][0]); acc[2][1] = fmaf(yv.z, wv.y, acc[2][1]);
            acc[2][2] = fmaf(yv.z, wv.z, acc[2][2]); acc[2][3] = fmaf(yv.z, wv.w, acc[2][3]);
            acc[3][0] = fmaf(yv.w, wv.x, acc[3][0]); acc[3][1] = fmaf(yv.w, wv.y, acc[3][1]);
            acc[3][2] = fmaf(yv.w, wv.z, acc[3][2]); acc[3][3] = fmaf(yv.w, wv.w, acc[3][3]);
        }
        float* ob = outp + b * 4096;
#pragma unroll
        for (int i = 0; i < 4; i++) {
            float4 o = make_float4(acc[i][0], acc[i][1], acc[i][2], acc[i][3]);
            *(float4*)&ob[(tl * 4 + i) * 64 + te * 4] = o;
        }
    }
}

// ============================================================================
extern "C" void kernel_launch(void* const* d_in, const int* in_sizes, int n_in,
                              void* d_out, int out_size) {
    const float* x    = (const float*)d_in[0];
    const float* c1w  = (const float*)d_in[1];
    const float* c1b  = (const float*)d_in[2];
    const float* c2w  = (const float*)d_in[3];
    const float* c2b  = (const float*)d_in[4];
    const float* c3w  = (const float*)d_in[5];
    const float* c3b  = (const float*)d_in[6];
    const float* lw   = (const float*)d_in[7];
    const float* lb   = (const float*)d_in[8];
    const float* ln1g = (const float*)d_in[9];
    const float* ln1b = (const float*)d_in[10];
    const float* in1w = (const float*)d_in[11];
    const float* cv1w = (const float*)d_in[12];
    const float* cv1b = (const float*)d_in[13];
    const float* xp1w = (const float*)d_in[14];
    const float* dt1w = (const float*)d_in[15];
    const float* dt1b = (const float*)d_in[16];
    const float* al1  = (const float*)d_in[17];
    const float* dp1  = (const float*)d_in[18];
    const float* ow1  = (const float*)d_in[19];
    const float* ln2g = (const float*)d_in[20];
    const float* ln2b = (const float*)d_in[21];
    const float* in2w = (const float*)d_in[22];
    const float* cv2w = (const float*)d_in[23];
    const float* cv2b = (const float*)d_in[24];
    const float* xp2w = (const float*)d_in[25];
    const float* dt2w = (const float*)d_in[26];
    const float* dt2b = (const float*)d_in[27];
    const float* al2  = (const float*)d_in[28];
    const float* dp2  = (const float*)d_in[29];
    const float* ow2  = (const float*)d_in[30];

    float *b1, *b2, *b3, *b4, *b5;
    cudaGetSymbolAddress((void**)&b1, g_buf1);
    cudaGetSymbolAddress((void**)&b2, g_buf2);
    cudaGetSymbolAddress((void**)&b3, g_buf3);
    cudaGetSymbolAddress((void**)&b4, g_buf4);
    cudaGetSymbolAddress((void**)&b5, g_buf5);

    const int smem_c3 = 20672 * 4;      // 82688 B
    const int smem_mb = 40448 * 4;      // 161792 B
    cudaFuncSetAttribute(k_conv3, cudaFuncAttributeMaxDynamicSharedMemorySize, smem_c3);
    cudaFuncSetAttribute(k_mamba, cudaFuncAttributeMaxDynamicSharedMemorySize, smem_mb);

    k_conv1<<<dim3(8, 512), 256>>>(x, c1w, c1b, b1);
    k_conv2<<<dim3(16, 512), 256>>>(b1, c2w, c2b, b2);
    k_conv3<<<dim3(4, 512), 256, smem_c3>>>(b2, c3w, c3b, b3);
    k_gemm<<<dim3(64, 8), 256>>>(b3, lw, lb, b4);
    k_mamba<<<512, 256, smem_mb>>>(b4, ln1g, ln1b, in1w, cv1w, cv1b, xp1w,
                                   dt1w, dt1b, al1, dp1, ow1, b5);
    k_mamba<<<512, 256, smem_mb>>>(b5, ln2g, ln2b, in2w, cv2w, cv2b, xp2w,
                                   dt2w, dt2b, al2, dp2, ow2, (float*)d_out);
}

// round 15
// speedup vs baseline: 1.1597x; 1.1597x over previous
#include <cuda_runtime.h>
#include <math.h>

// ---------------- scratch (static device allocation, no cudaMalloc) ----------------
__device__ float g_buf1[512 * 16 * 2048];   // conv1 out
__device__ float g_buf2[512 * 32 * 1024];   // conv2 out
__device__ float g_buf3[512 * 2048];        // conv3 + avgpool out (flattened features)
__device__ float g_buf4[512 * 4096];        // linear out  [B][64][64]
__device__ float g_buf5[512 * 4096];        // mamba1 out

// ============================================================================
// conv1 (1->16, k=5, pad=2) + relu + maxpool2.  x:[512,4096] -> out:[512,16,2048]
// ============================================================================
__global__ void k_conv1(const float* __restrict__ x, const float* __restrict__ w,
                        const float* __restrict__ bias, float* __restrict__ out) {
    __shared__ float xs[516];
    __shared__ float ws[80];
    __shared__ float bs[16];
    const int b = blockIdx.y;
    const int base = blockIdx.x * 256;          // output position base
    const int in_start = base * 2 - 2;
    const int tid = threadIdx.x;

    for (int i = tid; i < 516; i += 256) {
        int p = in_start + i;
        xs[i] = (p >= 0 && p < 4096) ? x[b * 4096 + p] : 0.f;
    }
    if (tid < 80) ws[tid] = w[tid];
    if (tid < 16) bs[tid] = bias[tid];
    __syncthreads();

    float xv[6];
#pragma unroll
    for (int j = 0; j < 6; j++) xv[j] = xs[2 * tid + j];

#pragma unroll
    for (int c = 0; c < 16; c++) {
        float a0 = 0.f, a1 = 0.f;
#pragma unroll
        for (int k = 0; k < 5; k++) {
            float wv = ws[c * 5 + k];
            a0 = fmaf(wv, xv[k], a0);
            a1 = fmaf(wv, xv[k + 1], a1);
        }
        out[(b * 16 + c) * 2048 + base + tid] = fmaxf(fmaxf(a0, a1) + bs[c], 0.f);
    }
}

// ============================================================================
// conv2 (16->32, k=5, pad=2) + relu + maxpool2. [512,16,2048] -> [512,32,1024]
// 256 threads = 16 oc-pairs x 16 pos-groups; 64 pooled outputs per block.
// Each thread: 2 oc x 8 conv positions (4 pooled). float4 x-loads, float2 w-loads.
// ============================================================================
__global__ void k_conv2(const float* __restrict__ in, const float* __restrict__ w,
                        const float* __restrict__ bias, float* __restrict__ out) {
    __shared__ float xs[16][132];
    __shared__ float ws[16 * 5 * 32];   // [ic][k][oc] transposed
    __shared__ float bs[32];
    const int b = blockIdx.y;
    const int base = blockIdx.x * 64;     // pooled output position base
    const int in_start = base * 2 - 2;
    const int tid = threadIdx.x;

    for (int idx = tid; idx < 16 * 132; idx += 256) {
        int ic = idx / 132, i = idx % 132;
        int p = in_start + i;
        xs[ic][i] = (p >= 0 && p < 2048) ? in[(b * 16 + ic) * 2048 + p] : 0.f;
    }
    for (int idx = tid; idx < 2560; idx += 256) {
        int oc = idx / 80, r = idx % 80;  // r = ic*5+k
        ws[r * 32 + oc] = w[idx];
    }
    if (tid < 32) bs[tid] = bias[tid];
    __syncthreads();

    const int ocp = tid & 15, pg = tid >> 4;
    const int cbase = pg * 8;             // conv-local base (8 conv positions)

    float acc[2][8];
#pragma unroll
    for (int o = 0; o < 2; o++)
#pragma unroll
        for (int q = 0; q < 8; q++) acc[o][q] = 0.f;

    for (int ic = 0; ic < 16; ic++) {
        float xv[12];
        *(float4*)&xv[0] = *(const float4*)&xs[ic][cbase];
        *(float4*)&xv[4] = *(const float4*)&xs[ic][cbase + 4];
        *(float4*)&xv[8] = *(const float4*)&xs[ic][cbase + 8];
        float wv[2][5];
#pragma unroll
        for (int k = 0; k < 5; k++) {
            float2 t = *(const float2*)&ws[(ic * 5 + k) * 32 + ocp * 2];
            wv[0][k] = t.x; wv[1][k] = t.y;
        }
#pragma unroll
        for (int o = 0; o < 2; o++)
#pragma unroll
            for (int q = 0; q < 8; q++)
#pragma unroll
                for (int k = 0; k < 5; k++)
                    acc[o][q] = fmaf(wv[o][k], xv[q + k], acc[o][q]);
    }
#pragma unroll
    for (int o = 0; o < 2; o++) {
        const int oc = ocp * 2 + o;
        const float bv = bs[oc];
#pragma unroll
        for (int i = 0; i < 4; i++) {
            float v = fmaxf(fmaxf(acc[o][2 * i], acc[o][2 * i + 1]) + bv, 0.f);
            out[(b * 32 + oc) * 1024 + base + pg * 4 + i] = v;
        }
    }
}

// ============================================================================
// conv3 (32->64, k=5, pad=2) + relu + adaptive avgpool(32) fused.
// [512,32,1024] -> [512,64,32] stored flat [512,2048]
// grid (4, 512): 8 pool windows per block. 256 threads = 32 oc-pairs x 8 pg.
// pg = {window-half (0..1), sub (0..3)}; 4 passes cover 8 windows.
// ============================================================================
__global__ void k_conv3(const float* __restrict__ in, const float* __restrict__ w,
                        const float* __restrict__ bias, float* __restrict__ out) {
    extern __shared__ float s3[];
    float* xs = s3;                 // [32][260]
    float* ws = s3 + 32 * 260;      // [ic][k][oc] = 10240
    float* bs = ws + 10240;         // 64
    float* red = bs + 64;           // [sub][oc][win] = 4*64*8

    const int b = blockIdx.y;
    const int wbase = blockIdx.x * 8;
    const int in_start = wbase * 32 - 2;
    const int tid = threadIdx.x;

    for (int idx = tid; idx < 32 * 260; idx += 256) {
        int ic = idx / 260, i = idx % 260;
        int p = in_start + i;
        xs[ic * 260 + i] = (p >= 0 && p < 1024) ? in[(b * 32 + ic) * 1024 + p] : 0.f;
    }
    for (int idx = tid; idx < 10240; idx += 256) {
        int oc = idx / 160, r = idx % 160;  // r = ic*5+k
        ws[r * 64 + oc] = w[idx];
    }
    if (tid < 64) bs[tid] = bias[tid];
    __syncthreads();

    const int ocp = tid & 31, pg = tid >> 5;
    const int sub = pg & 3, winh = pg >> 2;

    for (int wl2 = 0; wl2 < 4; wl2++) {
        const int win = wl2 * 2 + winh;
        const int xoff = win * 32 + sub * 8;
        float acc[2][8];
#pragma unroll
        for (int o = 0; o < 2; o++)
#pragma unroll
            for (int i = 0; i < 8; i++) acc[o][i] = 0.f;
        for (int ic = 0; ic < 32; ic++) {
            float xv[12];
            *(float4*)&xv[0] = *(const float4*)&xs[ic * 260 + xoff];
            *(float4*)&xv[4] = *(const float4*)&xs[ic * 260 + xoff + 4];
            *(float4*)&xv[8] = *(const float4*)&xs[ic * 260 + xoff + 8];
            float wv[2][5];
#pragma unroll
            for (int k = 0; k < 5; k++) {
                float2 t = *(const float2*)&ws[(ic * 5 + k) * 64 + ocp * 2];
                wv[0][k] = t.x; wv[1][k] = t.y;
            }
#pragma unroll
            for (int o = 0; o < 2; o++)
#pragma unroll
                for (int i = 0; i < 8; i++)
#pragma unroll
                    for (int k = 0; k < 5; k++)
                        acc[o][i] = fmaf(wv[o][k], xv[i + k], acc[o][i]);
        }
#pragma unroll
        for (int o = 0; o < 2; o++) {
            const int oc = ocp * 2 + o;
            const float bv = bs[oc];
            float part = 0.f;
#pragma unroll
            for (int i = 0; i < 8; i++) part += fmaxf(acc[o][i] + bv, 0.f);
            red[(sub * 64 + oc) * 8 + win] = part;
        }
    }
    __syncthreads();
    for (int idx = tid; idx < 512; idx += 256) {
        int o = idx >> 3, wl = idx & 7;
        float ssum = red[(0 * 64 + o) * 8 + wl] + red[(1 * 64 + o) * 8 + wl] +
                     red[(2 * 64 + o) * 8 + wl] + red[(3 * 64 + o) * 8 + wl];
        out[b * 2048 + o * 32 + wbase + wl] = ssum * (1.f / 32.f);
    }
}

// ============================================================================
// linear: C[512,4096] = A[512,2048] @ Bw[4096,2048]^T + bias
// 128x128 tile, BK=16, 256 threads, 8x8 microtile (4+4 split),
// single-sync ping-pong double buffering. grid (32, 4) = 128 CTAs (1 wave).
// ============================================================================
__global__ __launch_bounds__(256) void k_gemm(const float* __restrict__ A,
                                              const float* __restrict__ Bw,
                                              const float* __restrict__ bias,
                                              float* __restrict__ C) {
    __shared__ float As[2][16][132];
    __shared__ float Bs[2][16][132];
    const int bm = blockIdx.y * 128, bn = blockIdx.x * 128;
    const int tid = threadIdx.x;
    const int lr = tid >> 1;            // 0..127 tile row
    const int lk = (tid & 1) * 8;       // 0 or 8
    const int tx = tid & 15, ty = tid >> 4;

    const float* Ap = A + (bm + lr) * 2048 + lk;
    const float* Bp = Bw + (bn + lr) * 2048 + lk;

    float acc[8][8];
#pragma unroll
    for (int i = 0; i < 8; i++)
#pragma unroll
        for (int j = 0; j < 8; j++) acc[i][j] = 0.f;

    float4 a0v, a1v, b0v, b1v;
    // prefetch tile 0
    a0v = *(const float4*)(Ap);     a1v = *(const float4*)(Ap + 4);
    b0v = *(const float4*)(Bp);     b1v = *(const float4*)(Bp + 4);

#define GEMM_STS(bufi)                                                         \
    do {                                                                       \
        As[bufi][lk + 0][lr] = a0v.x; As[bufi][lk + 1][lr] = a0v.y;            \
        As[bufi][lk + 2][lr] = a0v.z; As[bufi][lk + 3][lr] = a0v.w;            \
        As[bufi][lk + 4][lr] = a1v.x; As[bufi][lk + 5][lr] = a1v.y;            \
        As[bufi][lk + 6][lr] = a1v.z; As[bufi][lk + 7][lr] = a1v.w;            \
        Bs[bufi][lk + 0][lr] = b0v.x; Bs[bufi][lk + 1][lr] = b0v.y;            \
        Bs[bufi][lk + 2][lr] = b0v.z; Bs[bufi][lk + 3][lr] = b0v.w;            \
        Bs[bufi][lk + 4][lr] = b1v.x; Bs[bufi][lk + 5][lr] = b1v.y;            \
        Bs[bufi][lk + 6][lr] = b1v.z; Bs[bufi][lk + 7][lr] = b1v.w;            \
    } while (0)

    GEMM_STS(0);
    __syncthreads();

    int buf = 0;
#pragma unroll 1
    for (int t = 0; t < 128; t++) {
        if (t < 127) {
            const float* Ap2 = Ap + (t + 1) * 16;
            const float* Bp2 = Bp + (t + 1) * 16;
            a0v = *(const float4*)(Ap2);     a1v = *(const float4*)(Ap2 + 4);
            b0v = *(const float4*)(Bp2);     b1v = *(const float4*)(Bp2 + 4);
        }
#pragma unroll
        for (int k = 0; k < 16; k++) {
            float4 a0 = *(const float4*)&As[buf][k][ty * 4];
            float4 a1 = *(const float4*)&As[buf][k][ty * 4 + 64];
            float4 b0 = *(const float4*)&Bs[buf][k][tx * 4];
            float4 b1 = *(const float4*)&Bs[buf][k][tx * 4 + 64];
            float ar[8] = {a0.x, a0.y, a0.z, a0.w, a1.x, a1.y, a1.z, a1.w};
            float br[8] = {b0.x, b0.y, b0.z, b0.w, b1.x, b1.y, b1.z, b1.w};
#pragma unroll
            for (int i = 0; i < 8; i++)
#pragma unroll
                for (int j = 0; j < 8; j++)
                    acc[i][j] = fmaf(ar[i], br[j], acc[i][j]);
        }
        if (t < 127) {
            buf ^= 1;
            GEMM_STS(buf);
        }
        __syncthreads();
    }
#undef GEMM_STS

    const float4 bv0 = *(const float4*)&bias[bn + tx * 4];
    const float4 bv1 = *(const float4*)&bias[bn + 64 + tx * 4];
#pragma unroll
    for (int g = 0; g < 2; g++) {
#pragma unroll
        for (int i = 0; i < 4; i++) {
            const int m = bm + g * 64 + ty * 4 + i;
            float* crow = C + m * 4096 + bn;
            const int r = g * 4 + i;
            float4 o0 = make_float4(acc[r][0] + bv0.x, acc[r][1] + bv0.y,
                                    acc[r][2] + bv0.z, acc[r][3] + bv0.w);
            float4 o1 = make_float4(acc[r][4] + bv1.x, acc[r][5] + bv1.y,
                                    acc[r][6] + bv1.z, acc[r][7] + bv1.w);
            *(float4*)(crow + tx * 4) = o0;
            *(float4*)(crow + 64 + tx * 4) = o1;
        }
    }
}

// ============================================================================
// fused layernorm + mamba block. One CTA per batch element, L=64, d=64.
// ============================================================================
__global__ void k_mamba(const float* __restrict__ xin,
                        const float* __restrict__ lng, const float* __restrict__ lnb,
                        const float* __restrict__ inw, const float* __restrict__ cvw,
                        const float* __restrict__ cvb, const float* __restrict__ xpw,
                        const float* __restrict__ dtw, const float* __restrict__ dtb,
                        const float* __restrict__ al,  const float* __restrict__ dp,
                        const float* __restrict__ ow,  float* __restrict__ outp) {
    extern __shared__ float s[];
    float* xT    = s;             // [64][68]  layernormed x, transposed [d][l]
    float* wT    = s + 4352;      // [64][132] in_w transposed [d][e]
    float* owT   = s + 12800;     // [64][68]  ow transposed [d][e]
    float* z_s   = s + 17152;     // [64][65]  [l][d]
    float* xi_s  = s + 21312;     // [64][65]
    float* u_s   = s + 25472;     // [64][65]
    float* dt_s  = s + 29632;     // [64][65]
    float* y2T   = s + 33792;     // [64][68]  [d][l]
    float* xdbl  = s + 38144;     // [64][13]
    float* xpw_s = s + 38976;     // 768
    float* dtw_s = s + 39744;     // 256
    float* dtb_s = s + 40000;
    float* cvw_s = s + 40064;     // 128
    float* cvb_s = s + 40192;
    float* dp_s  = s + 40256;
    float* lng_s = s + 40320;
    float* lnb_s = s + 40384;

    const int b = blockIdx.x, tid = threadIdx.x;
    const float* xb = xin + b * 4096;

    // ---- load weights (coalesced global, conflict-free transposed STS) ----
    for (int idx = tid; idx < 8192; idx += 256) {
        int e = idx >> 6, d = idx & 63;
        wT[d * 132 + e] = inw[idx];
    }
    for (int idx = tid; idx < 4096; idx += 256) {
        int e = idx >> 6, d = idx & 63;
        owT[d * 68 + e] = ow[idx];
    }
    for (int idx = tid; idx < 768; idx += 256) xpw_s[idx] = xpw[idx];
    dtw_s[tid] = dtw[tid];                      // exactly 256
    if (tid < 64) {
        dtb_s[tid] = dtb[tid]; cvb_s[tid] = cvb[tid]; dp_s[tid] = dp[tid];
        lng_s[tid] = lng[tid]; lnb_s[tid] = lnb[tid];
    }
    if (tid < 128) cvw_s[tid] = cvw[tid];
    __syncthreads();

    // ---- layernorm (4 threads per row), write transposed ----
    {
        const int l = tid >> 2, j = tid & 3;
        const float* row = xb + l * 64;
        float4 v[4];
#pragma unroll
        for (int i = 0; i < 4; i++) v[i] = *(const float4*)(row + j * 16 + i * 4);
        float sm = 0.f;
#pragma unroll
        for (int i = 0; i < 4; i++) sm += v[i].x + v[i].y + v[i].z + v[i].w;
        sm += __shfl_xor_sync(0xffffffffu, sm, 1);
        sm += __shfl_xor_sync(0xffffffffu, sm, 2);
        const float mean = sm * (1.f / 64.f);
        float vs = 0.f;
#pragma unroll
        for (int i = 0; i < 4; i++) {
            float a = v[i].x - mean, bb = v[i].y - mean, c = v[i].z - mean, dd = v[i].w - mean;
            vs += a * a + bb * bb + c * c + dd * dd;
        }
        vs += __shfl_xor_sync(0xffffffffu, vs, 1);
        vs += __shfl_xor_sync(0xffffffffu, vs, 2);
        const float rstd = rsqrtf(vs * (1.f / 64.f) + 1e-5f);
#pragma unroll
        for (int i = 0; i < 4; i++) {
            int d0 = j * 16 + i * 4;
            xT[(d0 + 0) * 68 + l] = (v[i].x - mean) * rstd * lng_s[d0 + 0] + lnb_s[d0 + 0];
            xT[(d0 + 1) * 68 + l] = (v[i].y - mean) * rstd * lng_s[d0 + 1] + lnb_s[d0 + 1];
            xT[(d0 + 2) * 68 + l] = (v[i].z - mean) * rstd * lng_s[d0 + 2] + lnb_s[d0 + 2];
            xT[(d0 + 3) * 68 + l] = (v[i].w - mean) * rstd * lng_s[d0 + 3] + lnb_s[d0 + 3];
        }
    }
    __syncthreads();

    // ---- in_proj: xz[l][e] = sum_d xT[d][l] * wT[d][e]   (4l x 8e microtile) ----
    {
        const int tl = tid & 15, te = tid >> 4;
        float acc[4][8];
#pragma unroll
        for (int i = 0; i < 4; i++)
#pragma unroll
            for (int j = 0; j < 8; j++) acc[i][j] = 0.f;
        const float* xcol = xT + tl * 4;
        const float* wcol = wT + te * 8;
        for (int d = 0; d < 64; d++) {
            float4 xv = *(const float4*)(xcol + d * 68);
            float4 w0 = *(const float4*)(wcol + d * 132);
            float4 w1 = *(const float4*)(wcol + d * 132 + 4);
            float xa[4] = {xv.x, xv.y, xv.z, xv.w};
#pragma unroll
            for (int i = 0; i < 4; i++) {
                acc[i][0] = fmaf(xa[i], w0.x, acc[i][0]);
                acc[i][1] = fmaf(xa[i], w0.y, acc[i][1]);
                acc[i][2] = fmaf(xa[i], w0.z, acc[i][2]);
                acc[i][3] = fmaf(xa[i], w0.w, acc[i][3]);
                acc[i][4] = fmaf(xa[i], w1.x, acc[i][4]);
                acc[i][5] = fmaf(xa[i], w1.y, acc[i][5]);
                acc[i][6] = fmaf(xa[i], w1.z, acc[i][6]);
                acc[i][7] = fmaf(xa[i], w1.w, acc[i][7]);
            }
        }
        const bool isz = (te >= 8);
        float* dst = isz ? z_s : xi_s;
        const int ebase = (isz ? (te - 8) : te) * 8;
#pragma unroll
        for (int i = 0; i < 4; i++)
#pragma unroll
            for (int j = 0; j < 8; j++)
                dst[(tl * 4 + i) * 65 + ebase + j] = acc[i][j];
    }
    __syncthreads();

    // ---- causal depthwise conv (k=2) + silu -> u ----
    for (int idx = tid; idx < 4096; idx += 256) {
        int l = idx >> 6, d = idx & 63;
        float xc = fmaf(cvw_s[d * 2 + 1], xi_s[l * 65 + d], cvb_s[d]);
        if (l > 0) xc = fmaf(cvw_s[d * 2], xi_s[(l - 1) * 65 + d], xc);
        u_s[l * 65 + d] = xc / (1.f + expf(-xc));
    }
    __syncthreads();

    // ---- x_proj: xdbl[l][j] = sum_d u[l][d] * xpw[j][d] ----
    for (int idx = tid; idx < 768; idx += 256) {
        int l = idx / 12, j = idx % 12;
        const float* ur = u_s + l * 65;
        const float* wr = xpw_s + j * 64;
        float sm = 0.f;
#pragma unroll 8
        for (int d = 0; d < 64; d++) sm = fmaf(ur[d], wr[d], sm);
        xdbl[l * 13 + j] = sm;
    }
    __syncthreads();

    // ---- dt = softplus(xdbl[:, :4] @ dtw^T + dtb) ----
    for (int idx = tid; idx < 4096; idx += 256) {
        int l = idx >> 6, d = idx & 63;
        float v = dtb_s[d];
#pragma unroll
        for (int r2 = 0; r2 < 4; r2++) v = fmaf(xdbl[l * 13 + r2], dtw_s[d * 4 + r2], v);
        dt_s[l * 65 + d] = fmaxf(v, 0.f) + log1pf(expf(-fabsf(v)));
    }
    __syncthreads();

    // ---- selective scan: thread (d = tid>>2, n = tid&3) ----
    {
        const int d = tid >> 2, n = tid & 3;
        const float A = -expf(al[d * 4 + n]);
        const float dpv = dp_s[d];
        float h = 0.f;
        for (int t = 0; t < 64; t++) {
            float dtv = dt_s[t * 65 + d];
            float uv = u_s[t * 65 + d];
            float Bv = xdbl[t * 13 + 4 + n];
            float Cv = xdbl[t * 13 + 8 + n];
            float dA = expf(dtv * A);
            h = fmaf(dA, h, dtv * Bv * uv);
            float yp = h * Cv;
            yp += __shfl_xor_sync(0xffffffffu, yp, 1);
            yp += __shfl_xor_sync(0xffffffffu, yp, 2);
            if (n == 0) {
                float zv = z_s[t * 65 + d];
                float yv = fmaf(dpv, uv, yp);
                y2T[d * 68 + t] = yv * (zv / (1.f + expf(-zv)));
            }
        }
    }
    __syncthreads();

    // ---- out_proj: out[l][e] = sum_d y2T[d][l] * owT[d][e]   (4x4 microtile) ----
    {
        const int tl = tid & 15, te = tid >> 4;
        float acc[4][4];
#pragma unroll
        for (int i = 0; i < 4; i++)
#pragma unroll
            for (int j = 0; j < 4; j++) acc[i][j] = 0.f;
        const float* ycol = y2T + tl * 4;
        const float* wcol = owT + te * 4;
        for (int d = 0; d < 64; d++) {
            float4 yv = *(const float4*)(ycol + d * 68);
            float4 wv = *(const float4*)(wcol + d * 68);
            acc[0][0] = fmaf(yv.x, wv.x, acc[0][0]); acc[0][1] = fmaf(yv.x, wv.y, acc[0][1]);
            acc[0][2] = fmaf(yv.x, wv.z, acc[0][2]); acc[0][3] = fmaf(yv.x, wv.w, acc[0][3]);
            acc[1][0] = fmaf(yv.y, wv.x, acc[1][0]); acc[1][1] = fmaf(yv.y, wv.y, acc[1][1]);
            acc[1][2] = fmaf(yv.y, wv.z, acc[1][2]); acc[1][3] = fmaf(yv.y, wv.w, acc[1][3]);
            acc[2][0] = fmaf(yv.z, wv.x, acc[2][0]); acc[2][1] = fmaf(yv.z, wv.y, acc[2][1]);
            acc[2][2] = fmaf(yv.z, wv.z, acc[2][2]); acc[2][3] = fmaf(yv.z, wv.w, acc[2][3]);
            acc[3][0] = fmaf(yv.w, wv.x, acc[3][0]); acc[3][1] = fmaf(yv.w, wv.y, acc[3][1]);
            acc[3][2] = fmaf(yv.w, wv.z, acc[3][2]); acc[3][3] = fmaf(yv.w, wv.w, acc[3][3]);
        }
        float* ob = outp + b * 4096;
#pragma unroll
        for (int i = 0; i < 4; i++) {
            float4 o = make_float4(acc[i][0], acc[i][1], acc[i][2], acc[i][3]);
            *(float4*)&ob[(tl * 4 + i) * 64 + te * 4] = o;
        }
    }
}

// ============================================================================
extern "C" void kernel_launch(void* const* d_in, const int* in_sizes, int n_in,
                              void* d_out, int out_size) {
    const float* x    = (const float*)d_in[0];
    const float* c1w  = (const float*)d_in[1];
    const float* c1b  = (const float*)d_in[2];
    const float* c2w  = (const float*)d_in[3];
    const float* c2b  = (const float*)d_in[4];
    const float* c3w  = (const float*)d_in[5];
    const float* c3b  = (const float*)d_in[6];
    const float* lw   = (const float*)d_in[7];
    const float* lb   = (const float*)d_in[8];
    const float* ln1g = (const float*)d_in[9];
    const float* ln1b = (const float*)d_in[10];
    const float* in1w = (const float*)d_in[11];
    const float* cv1w = (const float*)d_in[12];
    const float* cv1b = (const float*)d_in[13];
    const float* xp1w = (const float*)d_in[14];
    const float* dt1w = (const float*)d_in[15];
    const float* dt1b = (const float*)d_in[16];
    const float* al1  = (const float*)d_in[17];
    const float* dp1  = (const float*)d_in[18];
    const float* ow1  = (const float*)d_in[19];
    const float* ln2g = (const float*)d_in[20];
    const float* ln2b = (const float*)d_in[21];
    const float* in2w = (const float*)d_in[22];
    const float* cv2w = (const float*)d_in[23];
    const float* cv2b = (const float*)d_in[24];
    const float* xp2w = (const float*)d_in[25];
    const float* dt2w = (const float*)d_in[26];
    const float* dt2b = (const float*)d_in[27];
    const float* al2  = (const float*)d_in[28];
    const float* dp2  = (const float*)d_in[29];
    const float* ow2  = (const float*)d_in[30];

    float *b1, *b2, *b3, *b4, *b5;
    cudaGetSymbolAddress((void**)&b1, g_buf1);
    cudaGetSymbolAddress((void**)&b2, g_buf2);
    cudaGetSymbolAddress((void**)&b3, g_buf3);
    cudaGetSymbolAddress((void**)&b4, g_buf4);
    cudaGetSymbolAddress((void**)&b5, g_buf5);

    const int smem_c3 = 20672 * 4;      // 82688 B
    const int smem_mb = 40448 * 4;      // 161792 B
    cudaFuncSetAttribute(k_conv3, cudaFuncAttributeMaxDynamicSharedMemorySize, smem_c3);
    cudaFuncSetAttribute(k_mamba, cudaFuncAttributeMaxDynamicSharedMemorySize, smem_mb);

    k_conv1<<<dim3(8, 512), 256>>>(x, c1w, c1b, b1);
    k_conv2<<<dim3(16, 512), 256>>>(b1, c2w, c2b, b2);
    k_conv3<<<dim3(4, 512), 256, smem_c3>>>(b2, c3w, c3b, b3);
    k_gemm<<<dim3(32, 4), 256>>>(b3, lw, lb, b4);
    k_mamba<<<512, 256, smem_mb>>>(b4, ln1g, ln1b, in1w, cv1w, cv1b, xp1w,
                                   dt1w, dt1b, al1, dp1, ow1, b5);
    k_mamba<<<512, 256, smem_mb>>>(b5, ln2g, ln2b, in2w, cv2w, cv2b, xp2w,
                                   dt2w, dt2b, al2, dp2, ow2, (float*)d_out);
}